// round 1
// baseline (speedup 1.0000x reference)
#include <cuda_runtime.h>

#define HH 112
#define WW 112
#define CCH 64
#define BBATCH 32
#define TILE_H 16
#define SH_ROWS 20        // TILE_H + 4 halo
#define SH_COLS 116       // W + 4 halo
#define NTHREADS 224      // 112 cols x 2 row-halves

__global__ __launch_bounds__(NTHREADS)
void bionorm_kernel(const float* __restrict__ x,
                    const float* __restrict__ sigma,
                    const float* __restrict__ pow_p,
                    const float* __restrict__ sum_kernel,
                    const float* __restrict__ weight,
                    const float* __restrict__ bias,
                    float* __restrict__ out)
{
    __shared__ float xp_sh[SH_ROWS][SH_COLS];
    __shared__ float sf_sh[TILE_H][WW];
    __shared__ float kc_sh[25];
    __shared__ float sp_sh;

    const int tx  = threadIdx.x;          // 0..111 (column)
    const int ty  = threadIdx.y;          // 0..1   (row half)
    const int tid = ty * WW + tx;
    const int c   = blockIdx.y;
    const int b   = blockIdx.z;
    const int h0  = blockIdx.x * TILE_H;

    const float p = pow_p[c];
    const bool  sq = (p == 2.0f);

    if (tid < 25) kc_sh[tid] = sum_kernel[c * 25 + tid];
    if (tid == 0) {
        float s = sigma[c];
        sp_sh = sq ? s * s : powf(s, p);
    }

    const float* __restrict__ xin = x + (size_t)(b * CCH + c) * (HH * WW);

    // ---- Fill xp tile (rows h0-2..h0+17, cols -2..113, coords clamped) ----
    for (int idx = tid; idx < SH_ROWS * SH_COLS; idx += NTHREADS) {
        int r   = idx / SH_COLS;
        int cc2 = idx - r * SH_COLS;
        int gr  = h0 - 2 + r;
        gr = gr < 0 ? 0 : (gr > HH - 1 ? HH - 1 : gr);
        int gc  = cc2 - 2;
        gc = gc < 0 ? 0 : (gc > WW - 1 ? WW - 1 : gc);
        float v = xin[gr * WW + gc];
        xp_sh[r][cc2] = sq ? v * v : powf(v, p);
    }
    __syncthreads();

    // coefficients into registers
    float kc[25];
#pragma unroll
    for (int i = 0; i < 25; i++) kc[i] = kc_sh[i];

    // ---- Phase 1: window sums for 8 center rows at this column ----
    // Output column w uses clamped window column base wc = clamp(tx,2,109).
    const int wc = tx < 2 ? 2 : (tx > 109 ? 109 : tx);
    // center k (= ty*8+m) uses shared rows k..k+4, kernel row i = srow - k.
    float acc[8];
#pragma unroll
    for (int m = 0; m < 8; m++) acc[m] = 0.0f;

#pragma unroll
    for (int srl = 0; srl < 12; srl++) {
        const float* row = &xp_sh[ty * 8 + srl][wc];
        float v0 = row[0], v1 = row[1], v2 = row[2], v3 = row[3], v4 = row[4];
        const int mlo = (srl - 4) < 0 ? 0 : (srl - 4);
        const int mhi = srl < 7 ? srl : 7;
#pragma unroll
        for (int m = 0; m < 8; m++) {
            if (m >= mlo && m <= mhi) {     // constant-folds after unroll
                const int i = srl - m;      // kernel row
                acc[m] = fmaf(kc[i * 5 + 0], v0, acc[m]);
                acc[m] = fmaf(kc[i * 5 + 1], v1, acc[m]);
                acc[m] = fmaf(kc[i * 5 + 2], v2, acc[m]);
                acc[m] = fmaf(kc[i * 5 + 3], v3, acc[m]);
                acc[m] = fmaf(kc[i * 5 + 4], v4, acc[m]);
            }
        }
    }
#pragma unroll
    for (int m = 0; m < 8; m++) sf_sh[ty * 8 + m][tx] = acc[m];
    __syncthreads();

    // ---- Phase 2: out = w * xp / (sigma^p + sf_clamped) + b ----
    const float sp  = sp_sh;
    const float wgt = weight[c];
    const float bs  = bias[c];
    float* __restrict__ oimg = out + (size_t)(b * CCH + c) * (HH * WW);

#pragma unroll
    for (int m = 0; m < 8; m++) {
        const int k = ty * 8 + m;
        const int h = h0 + k;
        // row-replicated sf index (clamp window center to [2,109])
        int kidx = k;
        if (h < 2)   kidx = 2 - h0;
        if (h > 109) kidx = 109 - h0;
        float xpv = xp_sh[k + 2][tx + 2];
        float den = sp + sf_sh[kidx][tx];
        float val = __fdividef(wgt * xpv, den) + bs;
        oimg[h * WW + tx] = val;
    }
}

extern "C" void kernel_launch(void* const* d_in, const int* in_sizes, int n_in,
                              void* d_out, int out_size)
{
    const float* x          = (const float*)d_in[0];
    const float* sigma      = (const float*)d_in[1];
    const float* pow_p      = (const float*)d_in[2];
    const float* sum_kernel = (const float*)d_in[3];
    const float* weight     = (const float*)d_in[4];
    const float* bias       = (const float*)d_in[5];
    float* out = (float*)d_out;

    dim3 grid(HH / TILE_H, CCH, BBATCH);   // (7, 64, 32)
    dim3 block(WW, 2, 1);                  // 224 threads
    bionorm_kernel<<<grid, block>>>(x, sigma, pow_p, sum_kernel, weight, bias, out);
}

// round 4
// speedup vs baseline: 1.1793x; 1.1793x over previous
#include <cuda_runtime.h>

#define HH 112
#define WW 112
#define CCH 64
#define BBATCH 32
#define TILE_H 16
#define SH_ROWS 20        // TILE_H + 4 halo
#define SH_COLSF 116      // filled cols: global -2..113
#define SH_PITCH 120      // padded to multiple of 4 for float4
#define NTHREADS 224      // 112 cols x 2 row-halves

__global__ __launch_bounds__(NTHREADS)
void bionorm_kernel(const float* __restrict__ x,
                    const float* __restrict__ sigma,
                    const float* __restrict__ pow_p,
                    const float* __restrict__ sum_kernel,
                    const float* __restrict__ weight,
                    const float* __restrict__ bias,
                    float* __restrict__ out)
{
    __shared__ float xp_sh[SH_ROWS][SH_PITCH];
    __shared__ float buf[SH_ROWS][WW];      // fast: hsum[20][112]; general: sf[16][112]
    __shared__ float kc_sh[25];
    __shared__ float sp_sh;
    __shared__ int   uni_sh;

    const int tx  = threadIdx.x;          // 0..111 (column)
    const int ty  = threadIdx.y;          // 0..1   (row half)
    const int tid = ty * WW + tx;
    const int c   = blockIdx.y;
    const int b   = blockIdx.z;
    const int h0  = blockIdx.x * TILE_H;

    const float p  = pow_p[c];
    const bool  sq = (p == 2.0f);

    if (tid < 25) kc_sh[tid] = sum_kernel[c * 25 + tid];
    if (tid == 0) {
        float s = sigma[c];
        sp_sh = sq ? s * s : powf(s, p);
        const float* kp = sum_kernel + c * 25;
        float k0 = kp[0];
        int u = 1;
        #pragma unroll
        for (int i = 1; i < 25; i++) u &= (kp[i] == k0);
        uni_sh = u;
    }

    const float* __restrict__ xin = x + (size_t)(b * CCH + c) * (HH * WW);

    // ---- Fill xp tile (rows h0-2..h0+17, cols -2..113, coords clamped) ----
    for (int idx = tid; idx < SH_ROWS * SH_COLSF; idx += NTHREADS) {
        int r   = idx / SH_COLSF;
        int cc2 = idx - r * SH_COLSF;
        int gr  = h0 - 2 + r;
        gr = gr < 0 ? 0 : (gr > HH - 1 ? HH - 1 : gr);
        int gc  = cc2 - 2;
        gc = gc < 0 ? 0 : (gc > WW - 1 ? WW - 1 : gc);
        float v = xin[gr * WW + gc];
        xp_sh[r][cc2] = sq ? v * v : powf(v, p);
    }
    __syncthreads();

    const float sp  = sp_sh;
    const float wgt = weight[c];
    const float bs  = bias[c];
    float* __restrict__ oimg = out + (size_t)(b * CCH + c) * (HH * WW);

    if (uni_sh) {
        // ================= FAST PATH: separable box filter =================
        const float k0 = kc_sh[0];

        // Stage A: horizontal 5-tap sums -> buf[20][112], 4 outputs/task.
        // NOTE: entries at w<2 or w>109 are contaminated by the data halo and
        // are NEVER read (Stage B clamps the column index to [2,109], which
        // exactly reproduces the reference's edge-replication of the conv
        // output in w).
        for (int task = tid; task < SH_ROWS * 28; task += NTHREADS) {
            int r = task / 28;
            int w = (task - r * 28) * 4;
            const float4 a  = *(const float4*)&xp_sh[r][w];       // global cols w-2..w+1
            const float4 bb = *(const float4*)&xp_sh[r][w + 4];   // global cols w+2..w+5
            float s_mid = a.y + a.z + a.w;
            float h0s = s_mid + a.x + bb.x;
            float h1s = s_mid + bb.x + bb.y;
            float t_mid = bb.x + bb.y + bb.z;
            float h2s = a.z + a.w + t_mid;
            float h3s = a.w + t_mid + bb.w;
            *(float4*)&buf[r][w] = make_float4(h0s, h1s, h2s, h3s);
        }
        __syncthreads();

        // Stage B: vertical 5-tap via sliding window in registers.
        // Column clamp replicates conv output for w in {0,1,110,111}.
        const int wcc = tx < 2 ? 2 : (tx > 109 ? 109 : tx);
        float v[12];
        #pragma unroll
        for (int i = 0; i < 12; i++) v[i] = buf[ty * 8 + i][wcc];

        float sf[8];
        float s = v[0] + v[1] + v[2] + v[3] + v[4];
        sf[0] = s;
        #pragma unroll
        for (int m = 1; m < 8; m++) {
            s += v[m + 4] - v[m - 1];
            sf[m] = s;
        }
        #pragma unroll
        for (int m = 0; m < 8; m++) sf[m] *= k0;

        // vertical edge-replication fixup (row clamp of the conv output)
        if (h0 == 0 && ty == 0) { sf[0] = sf[2]; sf[1] = sf[2]; }
        if (h0 == HH - TILE_H && ty == 1) { sf[6] = sf[5]; sf[7] = sf[5]; }

        #pragma unroll
        for (int m = 0; m < 8; m++) {
            const int k = ty * 8 + m;
            const int h = h0 + k;
            float xpv = xp_sh[k + 2][tx + 2];
            float den = sp + sf[m];
            oimg[h * WW + tx] = __fdividef(wgt * xpv, den) + bs;
        }
    } else {
        // ================= GENERAL PATH: full 25-tap conv =================
        float kc[25];
        #pragma unroll
        for (int i = 0; i < 25; i++) kc[i] = kc_sh[i];

        const int wc = tx < 2 ? 2 : (tx > 109 ? 109 : tx);
        float acc[8];
        #pragma unroll
        for (int m = 0; m < 8; m++) acc[m] = 0.0f;

        #pragma unroll
        for (int srl = 0; srl < 12; srl++) {
            const float* row = &xp_sh[ty * 8 + srl][wc];
            float v0 = row[0], v1 = row[1], v2 = row[2], v3 = row[3], v4 = row[4];
            const int mlo = (srl - 4) < 0 ? 0 : (srl - 4);
            const int mhi = srl < 7 ? srl : 7;
            #pragma unroll
            for (int m = 0; m < 8; m++) {
                if (m >= mlo && m <= mhi) {
                    const int i = srl - m;
                    acc[m] = fmaf(kc[i * 5 + 0], v0, acc[m]);
                    acc[m] = fmaf(kc[i * 5 + 1], v1, acc[m]);
                    acc[m] = fmaf(kc[i * 5 + 2], v2, acc[m]);
                    acc[m] = fmaf(kc[i * 5 + 3], v3, acc[m]);
                    acc[m] = fmaf(kc[i * 5 + 4], v4, acc[m]);
                }
            }
        }
        #pragma unroll
        for (int m = 0; m < 8; m++) buf[ty * 8 + m][tx] = acc[m];
        __syncthreads();

        #pragma unroll
        for (int m = 0; m < 8; m++) {
            const int k = ty * 8 + m;
            const int h = h0 + k;
            int kidx = k;
            if (h < 2)        kidx = 2 - h0;
            if (h > HH - 3)   kidx = (HH - 3) - h0;
            float xpv = xp_sh[k + 2][tx + 2];
            float den = sp + buf[kidx][tx];
            oimg[h * WW + tx] = __fdividef(wgt * xpv, den) + bs;
        }
    }
}

extern "C" void kernel_launch(void* const* d_in, const int* in_sizes, int n_in,
                              void* d_out, int out_size)
{
    const float* x          = (const float*)d_in[0];
    const float* sigma      = (const float*)d_in[1];
    const float* pow_p      = (const float*)d_in[2];
    const float* sum_kernel = (const float*)d_in[3];
    const float* weight     = (const float*)d_in[4];
    const float* bias       = (const float*)d_in[5];
    float* out = (float*)d_out;

    dim3 grid(HH / TILE_H, CCH, BBATCH);   // (7, 64, 32)
    dim3 block(WW, 2, 1);                  // 224 threads
    bionorm_kernel<<<grid, block>>>(x, sigma, pow_p, sum_kernel, weight, bias, out);
}

// round 5
// speedup vs baseline: 1.7353x; 1.4715x over previous
#include <cuda_runtime.h>

#define HH 112
#define WW 112
#define CCH 64
#define BBATCH 32
#define TILE_H 16
#define SH_ROWS 20          // TILE_H + 4 halo rows
#define PITCH 120           // floats per shared row (row stride 480B, banks stagger)
#define BX 28               // float4 column groups
#define BY 8
#define NTHREADS (BX*BY)    // 224

__device__ __forceinline__ float frcp(float d) {
    float r; asm("rcp.approx.f32 %0, %1;" : "=f"(r) : "f"(d)); return r;
}
__device__ __forceinline__ int iclamp(int v, int lo, int hi) {
    return v < lo ? lo : (v > hi ? hi : v);
}

__global__ __launch_bounds__(NTHREADS)
void bionorm_kernel(const float* __restrict__ x,
                    const float* __restrict__ sigma,
                    const float* __restrict__ pow_p,
                    const float* __restrict__ sum_kernel,
                    const float* __restrict__ weight,
                    const float* __restrict__ bias,
                    float* __restrict__ out)
{
    __shared__ float xp_sh[SH_ROWS][PITCH];     // xp, cols 0..111 (no col halo)
    __shared__ float hs_sh[SH_ROWS][PITCH];     // horizontal 5-sums (cols 2..109 valid)
    __shared__ float kc_sh[25];
    __shared__ float sp_sh;
    __shared__ int   uni_sh;

    const int tx  = threadIdx.x;                // 0..27 column group
    const int ty  = threadIdx.y;                // 0..7
    const int tid = ty * BX + tx;
    const int c   = blockIdx.y;
    const int b   = blockIdx.z;
    const int h0  = blockIdx.x * TILE_H;
    const int w4  = 4 * tx;

    const float p  = pow_p[c];
    const bool  sq = (p == 2.0f);

    if (tid < 25) kc_sh[tid] = sum_kernel[c * 25 + tid];
    if (tid == 0) {
        float s = sigma[c];
        sp_sh = sq ? s * s : powf(s, p);
        const float* kp = sum_kernel + c * 25;
        float k0 = kp[0];
        int u = 1;
        #pragma unroll
        for (int i = 1; i < 25; i++) u &= (kp[i] == k0);
        uni_sh = u;
    }

    const float* __restrict__ xin = x + (size_t)(b * CCH + c) * (HH * WW);

    // ---- Fill: xp tile rows h0-2..h0+17 (row-clamped), aligned float4 ----
    #pragma unroll
    for (int r = ty; r < SH_ROWS; r += BY) {
        int gr = iclamp(h0 - 2 + r, 0, HH - 1);
        float4 v = *(const float4*)&xin[gr * WW + w4];
        float4 xp;
        if (sq) {
            xp.x = v.x * v.x; xp.y = v.y * v.y;
            xp.z = v.z * v.z; xp.w = v.w * v.w;
        } else {
            xp.x = powf(v.x, p); xp.y = powf(v.y, p);
            xp.z = powf(v.z, p); xp.w = powf(v.w, p);
        }
        *(float4*)&xp_sh[r][w4] = xp;
    }
    __syncthreads();

    const float sp  = sp_sh;
    const float wgt = weight[c];
    const float bs  = bias[c];
    float* __restrict__ oimg = out + (size_t)(b * CCH + c) * (HH * WW);

    if (uni_sh) {
        // ============ FAST PATH: separable box filter, 4-wide ============
        const float k0 = kc_sh[0];

        // Stage A: horizontal 5-tap sums. Lanes at w<2 / w>109 are garbage
        // (finite) and are replaced by register fixups in Stage B.
        const int li = tx > 0  ? w4 - 4 : 0;
        const int ri = tx < BX - 1 ? w4 + 4 : WW - 4;
        #pragma unroll
        for (int r = ty; r < SH_ROWS; r += BY) {
            const float* row = xp_sh[r];
            float4 A = *(const float4*)&row[w4];
            float4 L = *(const float4*)&row[li];
            float4 R = *(const float4*)&row[ri];
            float m = A.x + A.y + A.z;
            float t = A.w + R.x;
            float4 h;
            h.x = L.z + L.w + m;
            h.y = L.w + m + A.w;
            h.z = m + t;
            h.w = A.y + A.z + t + R.y;
            *(float4*)&hs_sh[r][w4] = h;
        }
        __syncthreads();

        // Stage B: vertical 5-tap with branchless row-replication clamp.
        // Thread outputs rows k=2ty and 2ty+1.
        const int ha  = h0 + 2 * ty;
        const int k0c = iclamp(ha,     2, HH - 3) - h0;   // clamped window base, row a
        const int k1c = iclamp(ha + 1, 2, HH - 3) - h0;   // row b (== k0c or k0c+1)
        float4 r0 = *(const float4*)&hs_sh[k0c + 0][w4];
        float4 r1 = *(const float4*)&hs_sh[k0c + 1][w4];
        float4 r2 = *(const float4*)&hs_sh[k0c + 2][w4];
        float4 r3 = *(const float4*)&hs_sh[k0c + 3][w4];
        float4 r4 = *(const float4*)&hs_sh[k0c + 4][w4];
        float4 r5 = *(const float4*)&hs_sh[k0c + 5][w4];

        float4 s0, s1;
        s0.x = r0.x + r1.x + r2.x + r3.x + r4.x;
        s0.y = r0.y + r1.y + r2.y + r3.y + r4.y;
        s0.z = r0.z + r1.z + r2.z + r3.z + r4.z;
        s0.w = r0.w + r1.w + r2.w + r3.w + r4.w;
        const bool adv = (k1c > k0c);
        s1.x = adv ? s0.x + r5.x - r0.x : s0.x;
        s1.y = adv ? s0.y + r5.y - r0.y : s0.y;
        s1.z = adv ? s0.z + r5.z - r0.z : s0.z;
        s1.w = adv ? s0.w + r5.w - r0.w : s0.w;

        // horizontal edge replication (conv-output clamp in w)
        if (tx == 0)      { s0.x = s0.z; s0.y = s0.z; s1.x = s1.z; s1.y = s1.z; }
        if (tx == BX - 1) { s0.z = s0.y; s0.w = s0.y; s1.z = s1.y; s1.w = s1.y; }

        // Output two float4 rows
        #pragma unroll
        for (int rr = 0; rr < 2; rr++) {
            const int k = 2 * ty + rr;
            const float4 sf = rr ? s1 : s0;
            float4 xp = *(const float4*)&xp_sh[k + 2][w4];
            float4 o;
            o.x = wgt * xp.x * frcp(fmaf(sf.x, k0, sp)) + bs;
            o.y = wgt * xp.y * frcp(fmaf(sf.y, k0, sp)) + bs;
            o.z = wgt * xp.z * frcp(fmaf(sf.z, k0, sp)) + bs;
            o.w = wgt * xp.w * frcp(fmaf(sf.w, k0, sp)) + bs;
            *(float4*)&oimg[(h0 + k) * WW + w4] = o;
        }
    } else {
        // ============ GENERAL PATH: full 25-tap conv (fallback) ============
        float res[2][4];
        #pragma unroll
        for (int rr = 0; rr < 2; rr++) {
            const int k = 2 * ty + rr;
            const int h = h0 + k;
            const int hc = iclamp(h, 2, HH - 3);
            const int kr = hc - h0;          // shared window base row
            #pragma unroll
            for (int j = 0; j < 4; j++) {
                const int w  = w4 + j;
                const int wc = iclamp(w, 2, WW - 3);
                float acc = 0.0f;
                #pragma unroll
                for (int i = 0; i < 5; i++) {
                    const float* row = &xp_sh[kr + i][wc - 2];
                    acc = fmaf(kc_sh[i * 5 + 0], row[0], acc);
                    acc = fmaf(kc_sh[i * 5 + 1], row[1], acc);
                    acc = fmaf(kc_sh[i * 5 + 2], row[2], acc);
                    acc = fmaf(kc_sh[i * 5 + 3], row[3], acc);
                    acc = fmaf(kc_sh[i * 5 + 4], row[4], acc);
                }
                float xpv = xp_sh[k + 2][w];
                res[rr][j] = wgt * xpv / (sp + acc) + bs;
            }
        }
        #pragma unroll
        for (int rr = 0; rr < 2; rr++) {
            const int h = h0 + 2 * ty + rr;
            float4 o = make_float4(res[rr][0], res[rr][1], res[rr][2], res[rr][3]);
            *(float4*)&oimg[h * WW + w4] = o;
        }
    }
}

extern "C" void kernel_launch(void* const* d_in, const int* in_sizes, int n_in,
                              void* d_out, int out_size)
{
    const float* x          = (const float*)d_in[0];
    const float* sigma      = (const float*)d_in[1];
    const float* pow_p      = (const float*)d_in[2];
    const float* sum_kernel = (const float*)d_in[3];
    const float* weight     = (const float*)d_in[4];
    const float* bias       = (const float*)d_in[5];
    float* out = (float*)d_out;

    dim3 grid(HH / TILE_H, CCH, BBATCH);   // (7, 64, 32)
    dim3 block(BX, BY, 1);                 // 224 threads
    bionorm_kernel<<<grid, block>>>(x, sigma, pow_p, sum_kernel, weight, bias, out);
}